// round 10
// baseline (speedup 1.0000x reference)
#include <cuda_runtime.h>
#include <stdint.h>

// Coarse key space: 128^3 = 2^21, key = (bx<<14)|(by<<7)|bz.
// Numeric key order == lexicographic row order of jnp.unique. No sort needed.
#define NKEYS      (1 << 21)
#define NWORDS     (NKEYS / 64)   // 32768 u64 presence words = 256 KB (L2-resident)
#define EMIT_BLKS  (NKEYS / 256)  // 8192 blocks for the emit partition
#define MAXN       600000

__device__ unsigned long long g_bits[NWORDS];  // presence bitmap
__device__ unsigned           g_wpfx[NWORDS];  // exclusive prefix (rank base) per word
__device__ int                g_winner[MAXN * 8]; // last-writer point idx per (rank, offset) slot

__device__ __forceinline__ unsigned pack_key(int cx, int cy, int cz) {
    return ((unsigned)(cx >> 1) << 14) | ((unsigned)(cy >> 1) << 7) | (unsigned)(cz >> 1);
}

// rank(key) from the L2-resident bitmap + per-word prefix. No rank array.
__device__ __forceinline__ unsigned rank_of(unsigned key) {
    unsigned long long word = g_bits[key >> 6];
    unsigned bit = key & 63u;
    return g_wpfx[key >> 6] + (unsigned)__popcll(word & ((1ull << bit) - 1ull));
}

// ---------------------------------------------------------------------------
// Fused init: clear bitmap (256 KB), winner = -1 (int4-vectorized, 16 MB),
// ucoords fill = -1.0f (6 MB). One launch.
__global__ void k_init(float* __restrict__ uc, int n) {
    int i = blockIdx.x * blockDim.x + threadIdx.x;
    if (i < NWORDS) g_bits[i] = 0ull;
    if (i < n * 2)  ((int4*)g_winner)[i] = make_int4(-1, -1, -1, -1);  // n*8 ints = n*2 int4
    if (i < n * 3)  uc[i] = -1.0f;
}

// Set presence bits. 500k atomicOr into a 256 KB L2-resident array.
__global__ void k_mark(const int* __restrict__ coords, int n) {
    int i = blockIdx.x * blockDim.x + threadIdx.x;
    if (i >= n) return;
    int cx = coords[3 * i], cy = coords[3 * i + 1], cz = coords[3 * i + 2];
    unsigned key = pack_key(cx, cy, cz);
    atomicOr(&g_bits[key >> 6], 1ull << (key & 63));
}

// Single-block full scan: 1024 threads x 32 words each. Per-thread popc +
// local prefix, one block scan of 1024 thread sums, store all 32768 wpfx.
// Everything lives in L2 (256 KB in, 128 KB out) -> ~3us, replaces two
// latency-bound 128-block kernels and an inter-kernel gap.
__global__ void k_scan() {
    int t = threadIdx.x;                 // 0..1023
    unsigned c[32];
    unsigned s = 0;
    const ulonglong2* p = (const ulonglong2*)(g_bits + t * 32);
    #pragma unroll
    for (int j = 0; j < 16; j++) {
        ulonglong2 w = p[j];
        c[2 * j]     = (unsigned)__popcll(w.x);
        c[2 * j + 1] = (unsigned)__popcll(w.y);
        s += c[2 * j] + c[2 * j + 1];
    }
    // block exclusive scan of s across 1024 threads
    unsigned lane = t & 31, w = t >> 5;          // 32 warps
    unsigned incl = s;
    #pragma unroll
    for (int o = 1; o < 32; o <<= 1) {
        unsigned x = __shfl_up_sync(0xFFFFFFFFu, incl, o);
        if (lane >= o) incl += x;
    }
    __shared__ unsigned wsum[32];
    if (lane == 31) wsum[w] = incl;
    __syncthreads();
    if (w == 0) {                                 // warp 0 scans the 32 warp sums
        unsigned v = wsum[lane];
        unsigned iv = v;
        #pragma unroll
        for (int o = 1; o < 32; o <<= 1) {
            unsigned x = __shfl_up_sync(0xFFFFFFFFu, iv, o);
            if (lane >= o) iv += x;
        }
        wsum[lane] = iv - v;                      // exclusive warp offsets
    }
    __syncthreads();
    unsigned run = wsum[w] + (incl - s);          // exclusive base for this thread
    unsigned* q = g_wpfx + t * 32;
    #pragma unroll
    for (int j = 0; j < 32; j++) { q[j] = run; run += c[j]; }
}

// Fused emit + winner (independent given wpfx; partitioned by blockIdx).
//  blocks [0, EMIT_BLKS): one thread per key — write sorted unique coarse
//    coords AS FLOATS (rows beyond U keep the -1.0f fill).
//  blocks [EMIT_BLKS, ...): one thread per point — last-index-wins arbitration
//    per (rank, offset) slot via atomicMax (matches sequential scatter).
__global__ void k_emit_winner(float* __restrict__ ucoords,
                              const int* __restrict__ coords, int n) {
    int b = blockIdx.x, t = threadIdx.x;
    if (b < EMIT_BLKS) {
        unsigned k = (unsigned)b * 256 + t;
        unsigned long long word = g_bits[k >> 6];
        unsigned bit = k & 63u;
        if (!((word >> bit) & 1ull)) return;
        unsigned r = g_wpfx[k >> 6] +
                     (unsigned)__popcll(word & ((1ull << bit) - 1ull));
        ucoords[3 * r]     = (float)(k >> 14);
        ucoords[3 * r + 1] = (float)((k >> 7) & 127u);
        ucoords[3 * r + 2] = (float)(k & 127u);
    } else {
        int i = (b - EMIT_BLKS) * 256 + t;
        if (i >= n) return;
        int cx = coords[3 * i], cy = coords[3 * i + 1], cz = coords[3 * i + 2];
        unsigned rank = rank_of(pack_key(cx, cy, cz));
        int off = ((cx & 1) << 2) | ((cy & 1) << 1) | (cz & 1);
        atomicMax(&g_winner[rank * 8 + off], i);
    }
}

// Row writer: one warp per output row (128 floats = 32 float4). Lane L owns
// float4 #L: slot = L>>2, quarter = L&3; lanes of a slot read a contiguous
// 64B feats segment. Every agg byte is written exactly once, streamed with
// .cs (never re-read — keep L2 for the bitmap/winner structures).
__global__ void k_rows(const float* __restrict__ feats,
                       float4* __restrict__ agg4, int n) {
    int warp = (blockIdx.x * blockDim.x + threadIdx.x) >> 5;
    int lane = threadIdx.x & 31;
    if (warp >= n) return;
    int slot = lane >> 2, q = lane & 3;
    int w = g_winner[warp * 8 + slot];
    float4 f = make_float4(0.f, 0.f, 0.f, 0.f);
    if (w >= 0) f = __ldg(&((const float4*)feats)[(size_t)w * 4 + q]);
    __stcs(&agg4[(size_t)warp * 32 + lane], f);
}

// Scalar fallback if agg isn't 16B-aligned (defensive; not expected).
__global__ void k_rows_scalar(const float* __restrict__ feats,
                              float* __restrict__ agg, int n) {
    long long g = (long long)blockIdx.x * blockDim.x + threadIdx.x;
    long long total = (long long)n * 128;
    if (g >= total) return;
    int r = (int)(g >> 7), c = (int)(g & 127);
    int w = g_winner[r * 8 + (c >> 4)];
    agg[g] = (w >= 0) ? feats[(size_t)w * 16 + (c & 15)] : 0.f;
}

// ---------------------------------------------------------------------------
extern "C" void kernel_launch(void* const* d_in, const int* in_sizes, int n_in,
                              void* d_out, int out_size) {
    // metadata order: feats (N*16 f32), coords (N*3 i32). Defensive swap check.
    int fi = 0, ci = 1;
    if (in_sizes[0] < in_sizes[1]) { fi = 1; ci = 0; }
    const float* feats  = (const float*)d_in[fi];
    const int*   coords = (const int*)d_in[ci];
    int n = in_sizes[ci] / 3;

    float* ucoords = (float*)d_out;                     // [n,3]  unique coarse coords AS FLOAT
    float* agg     = (float*)d_out + (size_t)n * 3;     // [n,128] aggregated features

    int initN = n * 3;                                   // covers n*2 int4s, n*3 floats, NWORDS
    if (n * 2 > initN) initN = n * 2;
    if (NWORDS > initN) initN = NWORDS;

    k_init<<<(initN + 255) / 256, 256>>>(ucoords, n);
    k_mark<<<(n + 255) / 256, 256>>>(coords, n);
    k_scan<<<1, 1024>>>();
    k_emit_winner<<<EMIT_BLKS + (n + 255) / 256, 256>>>(ucoords, coords, n);

    if ((((uintptr_t)agg) & 15) == 0) {
        k_rows<<<(n + 7) / 8, 256>>>(feats, (float4*)agg, n);   // 1 warp/row, 8 rows/block
    } else {
        long long total = (long long)n * 128;
        k_rows_scalar<<<(unsigned)((total + 255) / 256), 256>>>(feats, agg, n);
    }
}